// round 13
// baseline (speedup 1.0000x reference)
#include <cuda_runtime.h>
#include <cuda_fp16.h>
#include <math.h>
#include <stdint.h>

// Problem constants
#define B_SZ    2
#define S_LEN   2048
#define D_MODEL 2048
#define NHEAD   8
#define HDIM    256
#define BSTOT   (B_SZ * S_LEN)   // 4096
#define NQKV    (D_MODEL + 2 * HDIM)   // 2560
#define QKVP    NQKV

// Scratch (static __device__ arrays — allocation-free rule)
__device__ __half g_X  [(size_t)BSTOT * D_MODEL];
__device__ __half g_WT [(size_t)NQKV * D_MODEL];
__device__ __half g_WoT[(size_t)D_MODEL * D_MODEL];
__device__ __half g_QKV[(size_t)BSTOT * NQKV];
__device__ __half g_ctx[(size_t)BSTOT * D_MODEL];

// ---------------------------------------------------------------------------
// helpers
// ---------------------------------------------------------------------------
__device__ __forceinline__ uint32_t smem_u32(const void* p) {
    uint32_t a;
    asm("{ .reg .u64 t; cvta.to.shared.u64 t, %1; cvt.u32.u64 %0, t; }"
        : "=r"(a) : "l"(p));
    return a;
}

#define CP_ASYNC16(dst, src) \
    asm volatile("cp.async.cg.shared.global [%0], [%1], 16;" :: "r"(dst), "l"(src) : "memory")
#define CP_COMMIT()  asm volatile("cp.async.commit_group;" ::: "memory")
#define CP_WAIT(n)   asm volatile("cp.async.wait_group %0;" :: "n"(n) : "memory")

__device__ __forceinline__ void mma_fp16(float c[4], const uint32_t a[4], const uint32_t b[2]) {
    asm volatile(
        "mma.sync.aligned.m16n8k16.row.col.f32.f16.f16.f32 "
        "{%0,%1,%2,%3}, {%4,%5,%6,%7}, {%8,%9}, {%0,%1,%2,%3};"
        : "+f"(c[0]), "+f"(c[1]), "+f"(c[2]), "+f"(c[3])
        : "r"(a[0]), "r"(a[1]), "r"(a[2]), "r"(a[3]), "r"(b[0]), "r"(b[1]));
}
__device__ __forceinline__ void ldsm4(uint32_t r[4], uint32_t addr) {
    asm volatile("ldmatrix.sync.aligned.m8n8.x4.shared.b16 {%0,%1,%2,%3}, [%4];"
        : "=r"(r[0]), "=r"(r[1]), "=r"(r[2]), "=r"(r[3]) : "r"(addr));
}
__device__ __forceinline__ void ldsm4t(uint32_t r[4], uint32_t addr) {
    asm volatile("ldmatrix.sync.aligned.m8n8.x4.trans.shared.b16 {%0,%1,%2,%3}, [%4];"
        : "=r"(r[0]), "=r"(r[1]), "=r"(r[2]), "=r"(r[3]) : "r"(addr));
}

// output stores (fp16 or fp32 C)
__device__ __forceinline__ void store_pair(__half* C, size_t idx, float a, float b) {
    *(__half2*)(C + idx) = __floats2half2_rn(a, b);
}
__device__ __forceinline__ void store_pair(float* C, size_t idx, float a, float b) {
    *(float2*)(C + idx) = make_float2(a, b);
}

// ---------------------------------------------------------------------------
// fp16 mma.sync GEMM (R11-proven): C[M,N] = A[M,K] @ Bt[N,K]^T
// CTA 128x128, BK=64, 8 warps, warp tile 64x32, 3-stage cp.async + ldmatrix.
// ---------------------------------------------------------------------------
#define GSTAGES 3
#define GP      72                    // smem pitch (halves)
#define TILE_H  (128 * GP)
#define STAGE_B (2 * TILE_H * 2)      // 36,864 B (A+B)
#define GSMEM_BYTES (GSTAGES * STAGE_B)   // 110,592 B

template <typename OutT>
__global__ __launch_bounds__(256, 2) void gemm_fp16(
    const __half* __restrict__ A, const __half* __restrict__ Bt,
    OutT* __restrict__ C, int N, int K)
{
    extern __shared__ __align__(16) char smc[];
    const uint32_t sb = smem_u32(smc);

    const int tid  = threadIdx.x;
    const int wid  = tid >> 5;
    const int lane = tid & 31;
    const int wm   = wid >> 2;
    const int wn   = wid & 3;
    const int lr   = lane >> 2;
    const int lc   = lane & 3;
    const int m0   = blockIdx.y << 7;
    const int n0   = blockIdx.x << 7;
    const int KT   = K >> 6;

    const int t8   = lane >> 3;
    const int trow = lane & 7;
    const uint32_t aOff = (uint32_t)((wm * 64 + (t8 & 1) * 8 + trow) * GP + ((t8 >> 1) << 3)) * 2;
    const uint32_t bOff = (uint32_t)((wn * 32 + (t8 >> 1) * 8 + trow) * GP + ((t8 & 1) << 3)) * 2;

    const __half* Ag = A  + (size_t)m0 * K;
    const __half* Bg = Bt + (size_t)n0 * K;

    float acc[4][4][4];
#pragma unroll
    for (int i = 0; i < 4; i++)
#pragma unroll
        for (int j = 0; j < 4; j++)
#pragma unroll
            for (int v = 0; v < 4; v++) acc[i][j][v] = 0.f;

    auto load_tile = [&](int s, int kt) {
        const __half* ag = Ag + kt * 64;
        const __half* bg = Bg + kt * 64;
        uint32_t sa = sb + (uint32_t)s * STAGE_B;
        uint32_t sbb = sa + TILE_H * 2;
        int idx = tid;
#pragma unroll
        for (int i = 0; i < 4; i++, idx += 256) {
            int row = idx >> 3;
            int c8  = (idx & 7) << 3;
            uint32_t off = (uint32_t)(row * GP + c8) * 2;
            CP_ASYNC16(sa + off,  ag + (size_t)row * K + c8);
            CP_ASYNC16(sbb + off, bg + (size_t)row * K + c8);
        }
    };

#pragma unroll
    for (int s = 0; s < GSTAGES - 1; s++) {
        load_tile(s, s);
        CP_COMMIT();
    }

    for (int kt = 0; kt < KT; kt++) {
        CP_WAIT(GSTAGES - 2);
        __syncthreads();

        if (kt + GSTAGES - 1 < KT) load_tile((kt + GSTAGES - 1) % GSTAGES, kt + GSTAGES - 1);
        CP_COMMIT();

        const uint32_t aBase = sb + (uint32_t)((kt % GSTAGES) * STAGE_B) + aOff;
        const uint32_t bBase = aBase - aOff + TILE_H * 2 + bOff;

#pragma unroll
        for (int kk = 0; kk < 64; kk += 16) {
            uint32_t a[4][4], b[2][4];
            ldsm4(a[0], aBase + (uint32_t)kk * 2);
            ldsm4(b[0], bBase + (uint32_t)kk * 2);
            ldsm4(b[1], bBase + (uint32_t)(16 * GP + kk) * 2);
            ldsm4(a[1], aBase + (uint32_t)(1 * 16 * GP + kk) * 2);
            ldsm4(a[2], aBase + (uint32_t)(2 * 16 * GP + kk) * 2);
            ldsm4(a[3], aBase + (uint32_t)(3 * 16 * GP + kk) * 2);
#pragma unroll
            for (int mt = 0; mt < 4; mt++)
#pragma unroll
                for (int nt = 0; nt < 4; nt++)
                    mma_fp16(acc[mt][nt], a[mt], &b[nt >> 1][(nt & 1) * 2]);
        }
    }

#pragma unroll
    for (int mt = 0; mt < 4; mt++) {
        int r0 = m0 + wm * 64 + mt * 16 + lr;
#pragma unroll
        for (int nt = 0; nt < 4; nt++) {
            int c = n0 + wn * 32 + nt * 8 + lc * 2;
            store_pair(C, (size_t)r0 * N + c,       acc[mt][nt][0], acc[mt][nt][1]);
            store_pair(C, (size_t)(r0 + 8) * N + c, acc[mt][nt][2], acc[mt][nt][3]);
        }
    }
}

// ---------------------------------------------------------------------------
// Prep kernels (fp16 outputs)
// ---------------------------------------------------------------------------
__global__ void transpose_qkv(const float* __restrict__ Wq,
                              const float* __restrict__ Wk,
                              const float* __restrict__ Wv,
                              __half* __restrict__ out) {
    __shared__ float t[32][33];
    int n0 = blockIdx.x * 32;
    int k0 = blockIdx.y * 32;
    int x = threadIdx.x, y = threadIdx.y;  // (32, 8)

    const float* src;
    int scol, pitch;
    if (n0 < D_MODEL)              { src = Wq; scol = n0;                  pitch = D_MODEL; }
    else if (n0 < D_MODEL + HDIM)  { src = Wk; scol = n0 - D_MODEL;        pitch = HDIM; }
    else                           { src = Wv; scol = n0 - D_MODEL - HDIM; pitch = HDIM; }

#pragma unroll
    for (int j = 0; j < 32; j += 8)
        t[y + j][x] = src[(size_t)(k0 + y + j) * pitch + scol + x];
    __syncthreads();
#pragma unroll
    for (int j = 0; j < 32; j += 8)
        out[(size_t)(n0 + y + j) * D_MODEL + k0 + x] = __float2half_rn(t[x][y + j]);
}

__global__ void transpose_wo(const float* __restrict__ in, __half* __restrict__ out,
                             int rows, int cols) {
    __shared__ float t[32][33];
    int c0 = blockIdx.x * 32, r0 = blockIdx.y * 32;
    int x = threadIdx.x, y = threadIdx.y;  // (32, 8)
#pragma unroll
    for (int j = 0; j < 32; j += 8)
        t[y + j][x] = in[(size_t)(r0 + y + j) * cols + c0 + x];
    __syncthreads();
#pragma unroll
    for (int j = 0; j < 32; j += 8)
        out[(size_t)(c0 + y + j) * rows + r0 + x] = __float2half_rn(t[x][y + j]);
}

__global__ void cvt_fp16_kernel(const float4* __restrict__ in, __half2* __restrict__ out) {
    size_t i = (size_t)blockIdx.x * blockDim.x + threadIdx.x;
    float4 v = in[i];
    out[2 * i]     = __floats2half2_rn(v.x, v.y);
    out[2 * i + 1] = __floats2half2_rn(v.z, v.w);
}

// ---------------------------------------------------------------------------
// RoPE in-place on fused fp16 QKV (Q all heads + K slice).
// ---------------------------------------------------------------------------
__global__ void rope_kernel(__half* __restrict__ QKV) {
    const int bs  = blockIdx.x;
    const int d   = threadIdx.x;          // 0..127
    const int pos = bs & (S_LEN - 1);

    const double inv = exp(-((double)(2 * d) / (double)HDIM) * 9.210340371976184);
    const double ang = (double)pos * inv;
    const double red = ang - 6.283185307179586 * rint(ang * 0.15915494309189535);
    float sn, c;
    sincosf((float)red, &sn, &c);

    __half* row = QKV + (size_t)bs * QKVP;
#pragma unroll
    for (int h = 0; h < NHEAD; h++) {
        float q1 = __half2float(row[h * HDIM + d]);
        float q2 = __half2float(row[h * HDIM + 128 + d]);
        row[h * HDIM + d]       = __float2half_rn(q1 * c - q2 * sn);
        row[h * HDIM + 128 + d] = __float2half_rn(q2 * c + q1 * sn);
    }
    __half* krow = row + D_MODEL;
    float k1 = __half2float(krow[d]), k2 = __half2float(krow[128 + d]);
    krow[d]       = __float2half_rn(k1 * c - k2 * sn);
    krow[128 + d] = __float2half_rn(k2 * c + k1 * sn);
}

// ---------------------------------------------------------------------------
// fp16 tensor-core flash attention, BM=128, 512 threads (16 warps).
// R11-proven 5-sync schedule; iteration count & K/V traffic halved vs BM=64.
// S warp grid 8m x 2n (tile 16x32); PV warp grid 4m x 4n (tile 32x64).
// ---------------------------------------------------------------------------
#define APH 264   // Q/K/V pitch (halves)
#define PPH 72    // P pitch (halves)
#define ATTN_HALVES (128 * APH + 64 * APH + 64 * APH + 128 * PPH)   // 76,800
#define ATTN_SMEM (ATTN_HALVES * 2 + 896 * 4)   // 157,184 B

__global__ __launch_bounds__(512, 1) void attn_fp16(
        const __half* __restrict__ QKV, __half* __restrict__ ctx) {
    extern __shared__ __align__(16) char smc[];
    __half* Qs = (__half*)smc;           // [128][264]
    __half* Ks = Qs + 128 * APH;         // [64][264]
    __half* Vs = Ks + 64 * APH;          // [64][264]  (rows = keys, cols = d)
    __half* Ps = Vs + 64 * APH;          // [128][72]
    float* pmax = (float*)(smc + ATTN_HALVES * 2);  // [2][128] by n-group
    float* psum = pmax + 256;                        // [2][128]
    float* mS   = psum + 256;                        // [128]
    float* lS   = mS + 128;                          // [128]
    float* aS   = lS + 128;                          // [128]

    const uint32_t qs_u = smem_u32(Qs);
    const uint32_t ks_u = smem_u32(Ks);
    const uint32_t vs_u = smem_u32(Vs);
    const uint32_t ps_u = smem_u32(Ps);

    const int qbi = (int)gridDim.x - 1 - (int)blockIdx.x;  // heavy blocks first
    const int b   = blockIdx.y >> 3;
    const int h   = blockIdx.y & 7;
    const int tid = threadIdx.x;
    const int wid = tid >> 5;
    const int lane = tid & 31;
    const int lr  = lane >> 2;
    const int lc  = lane & 3;

    const int smw = (wid & 7) << 4;    // S-phase m: 0..112
    const int g   = wid >> 3;          // S-phase n group (0/1)
    const int snw = g << 5;
    const int pm  = (wid & 3) << 5;    // PV m: 0..96
    const int pn  = (wid >> 2) << 6;   // PV n: 0,64,128,192

    const int t8   = lane >> 3;
    const int trow = lane & 7;
    const uint32_t qOff = (uint32_t)((smw + (t8 & 1) * 8 + trow) * APH + ((t8 >> 1) << 3)) * 2;
    const uint32_t kOff = (uint32_t)((snw + (t8 >> 1) * 8 + trow) * APH + ((t8 & 1) << 3)) * 2;
    const uint32_t pOff = (uint32_t)((pm + (t8 & 1) * 8 + trow) * PPH + ((t8 >> 1) << 3)) * 2;
    const uint32_t vOff = (uint32_t)(((t8 & 1) * 8 + trow) * APH + pn + ((t8 >> 1) << 3)) * 2;

    const __half* Kg = QKV + (size_t)b * S_LEN * QKVP + D_MODEL;
    const __half* Vg = Kg + HDIM;
    const float scale = 0.0625f;
    const int kb_last = 2 * qbi + 1;

    auto load_K = [&](int kb) {
        const __half* kt = Kg + (size_t)kb * 64 * QKVP;
        int idx = tid;
#pragma unroll
        for (int i = 0; i < 4; i++, idx += 512) {
            int row = idx >> 5;
            int c8  = (idx & 31) << 3;
            CP_ASYNC16(ks_u + (uint32_t)(row * APH + c8) * 2,
                       kt + (size_t)row * QKVP + c8);
        }
    };
    auto load_V = [&](int kb) {
        const __half* vt = Vg + (size_t)kb * 64 * QKVP;
        int idx = tid;
#pragma unroll
        for (int i = 0; i < 4; i++, idx += 512) {
            int row = idx >> 5;
            int c8  = (idx & 31) << 3;
            CP_ASYNC16(vs_u + (uint32_t)(row * APH + c8) * 2,
                       vt + (size_t)row * QKVP + c8);
        }
    };

    // prologue: group A = [Q tile (128 rows) + K(0)], group B = [V(0)]
    {
        const __half* Qg = QKV + (size_t)(b * S_LEN + qbi * 128) * QKVP + h * HDIM;
        int idx = tid;
#pragma unroll
        for (int i = 0; i < 8; i++, idx += 512) {
            int row = idx >> 5;
            int c8  = (idx & 31) << 3;
            CP_ASYNC16(qs_u + (uint32_t)(row * APH + c8) * 2,
                       Qg + (size_t)row * QKVP + c8);
        }
        load_K(0);
        CP_COMMIT();
        load_V(0);
        CP_COMMIT();
    }
    if (tid < 128) { mS[tid] = -INFINITY; lS[tid] = 0.f; }

    float oacc[2][8][4];
#pragma unroll
    for (int mt = 0; mt < 2; mt++)
#pragma unroll
        for (int nt = 0; nt < 8; nt++)
#pragma unroll
            for (int v = 0; v < 4; v++) oacc[mt][nt][v] = 0.f;

    for (int kb = 0; kb <= kb_last; kb++) {
        CP_WAIT(1);          // K(kb) ready; V(kb) may still be in flight
        __syncthreads();

        // ---- S = Q K^T (fp16 k16) ----
        float sacc[4][4];
#pragma unroll
        for (int nt = 0; nt < 4; nt++)
#pragma unroll
            for (int v = 0; v < 4; v++) sacc[nt][v] = 0.f;

#pragma unroll 4
        for (int k = 0; k < HDIM; k += 16) {
            uint32_t af[4], bf[2][4];
            ldsm4(af, qs_u + qOff + (uint32_t)k * 2);
            ldsm4(bf[0], ks_u + kOff + (uint32_t)k * 2);
            ldsm4(bf[1], ks_u + kOff + (uint32_t)(16 * APH + k) * 2);
#pragma unroll
            for (int nt = 0; nt < 4; nt++)
                mma_fp16(sacc[nt], af, &bf[nt >> 1][(nt & 1) * 2]);
        }

        // ---- scale + mask (fp32 regs; global-index shift) ----
        const bool diag = (kb >= 2 * qbi);
        const int shift = kb * 64 - qbi * 128;   // 0 or 64 on diag tiles
        const int r0 = smw + lr, r1 = r0 + 8;
#pragma unroll
        for (int nt = 0; nt < 4; nt++) {
            int c0 = snw + nt * 8 + 2 * lc + shift;
            sacc[nt][0] *= scale; sacc[nt][1] *= scale;
            sacc[nt][2] *= scale; sacc[nt][3] *= scale;
            if (diag) {
                if (c0 > r0)     sacc[nt][0] = -INFINITY;
                if (c0 + 1 > r0) sacc[nt][1] = -INFINITY;
                if (c0 > r1)     sacc[nt][2] = -INFINITY;
                if (c0 + 1 > r1) sacc[nt][3] = -INFINITY;
            }
        }

        // ---- row-max partials ----
        float m0p = -INFINITY, m1p = -INFINITY;
#pragma unroll
        for (int nt = 0; nt < 4; nt++) {
            m0p = fmaxf(m0p, fmaxf(sacc[nt][0], sacc[nt][1]));
            m1p = fmaxf(m1p, fmaxf(sacc[nt][2], sacc[nt][3]));
        }
        m0p = fmaxf(m0p, __shfl_xor_sync(0xffffffffu, m0p, 1));
        m0p = fmaxf(m0p, __shfl_xor_sync(0xffffffffu, m0p, 2));
        m1p = fmaxf(m1p, __shfl_xor_sync(0xffffffffu, m1p, 1));
        m1p = fmaxf(m1p, __shfl_xor_sync(0xffffffffu, m1p, 2));
        if (lc == 0) { pmax[g * 128 + r0] = m0p; pmax[g * 128 + r1] = m1p; }
        __syncthreads();   // pmax visible; Ks fully consumed

        if (kb < kb_last) load_K(kb + 1);   // overlaps softmax + PV
        CP_COMMIT();

        // ---- exp on regs, fp16 P, partial sums ----
        float mnew0 = fmaxf(mS[r0], fmaxf(pmax[r0], pmax[128 + r0]));
        float mnew1 = fmaxf(mS[r1], fmaxf(pmax[r1], pmax[128 + r1]));
        float s0 = 0.f, s1 = 0.f;
#pragma unroll
        for (int nt = 0; nt < 4; nt++) {
            int c0 = snw + nt * 8 + 2 * lc;
            float p0 = __expf(sacc[nt][0] - mnew0);
            float p1 = __expf(sacc[nt][1] - mnew0);
            float p2 = __expf(sacc[nt][2] - mnew1);
            float p3 = __expf(sacc[nt][3] - mnew1);
            s0 += p0 + p1; s1 += p2 + p3;
            *(__half2*)(Ps + r0 * PPH + c0) = __floats2half2_rn(p0, p1);
            *(__half2*)(Ps + r1 * PPH + c0) = __floats2half2_rn(p2, p3);
        }
        s0 += __shfl_xor_sync(0xffffffffu, s0, 1);
        s0 += __shfl_xor_sync(0xffffffffu, s0, 2);
        s1 += __shfl_xor_sync(0xffffffffu, s1, 1);
        s1 += __shfl_xor_sync(0xffffffffu, s1, 2);
        if (lc == 0) { psum[g * 128 + r0] = s0; psum[g * 128 + r1] = s1; }

        CP_WAIT(1);          // V(kb) ready; K(kb+1) stays in flight
        __syncthreads();     // psum/Ps visible; Vs ready

        // ---- single-writer stats update (warps 0-7 cover all 128 rows) ----
        if (g == 0 && lc == 0) {
            float mnew0w = fmaxf(mS[r0], fmaxf(pmax[r0], pmax[128 + r0]));
            float mnew1w = fmaxf(mS[r1], fmaxf(pmax[r1], pmax[128 + r1]));
            float a0 = __expf(mS[r0] - mnew0w);
            float a1 = __expf(mS[r1] - mnew1w);
            lS[r0] = lS[r0] * a0 + psum[r0] + psum[128 + r0];
            lS[r1] = lS[r1] * a1 + psum[r1] + psum[128 + r1];
            mS[r0] = mnew0w; mS[r1] = mnew1w;
            aS[r0] = a0;     aS[r1] = a1;
        }
        __syncthreads();     // aS/lS visible

        // ---- O rescale + O += P @ V (V B-frags via ldmatrix.trans) ----
        {
            float a00 = aS[pm + lr];
            float a01 = aS[pm + lr + 8];
            float a10 = aS[pm + 16 + lr];
            float a11 = aS[pm + 24 + lr];
#pragma unroll
            for (int nt = 0; nt < 8; nt++) {
                oacc[0][nt][0] *= a00; oacc[0][nt][1] *= a00;
                oacc[0][nt][2] *= a01; oacc[0][nt][3] *= a01;
                oacc[1][nt][0] *= a10; oacc[1][nt][1] *= a10;
                oacc[1][nt][2] *= a11; oacc[1][nt][3] *= a11;
            }
#pragma unroll
            for (int k = 0; k < 64; k += 16) {
                uint32_t aP0[4], aP1[4], bv[4][4];
                ldsm4(aP0, ps_u + pOff + (uint32_t)k * 2);
                ldsm4(aP1, ps_u + pOff + (uint32_t)(16 * PPH + k) * 2);
#pragma unroll
                for (int nn = 0; nn < 4; nn++)
                    ldsm4t(bv[nn], vs_u + vOff + (uint32_t)(k * APH + nn * 16) * 2);
#pragma unroll
                for (int nt = 0; nt < 8; nt++) {
                    mma_fp16(oacc[0][nt], aP0, &bv[nt >> 1][(nt & 1) * 2]);
                    mma_fp16(oacc[1][nt], aP1, &bv[nt >> 1][(nt & 1) * 2]);
                }
            }
        }
        __syncthreads();   // Vs reads done

        if (kb < kb_last) load_V(kb + 1);   // overlaps next S + softmax
        CP_COMMIT();
    }

    // ---- normalize + write ctx (fp16) ----
    {
        float li[4];
        li[0] = 1.f / lS[pm + lr];
        li[1] = 1.f / lS[pm + lr + 8];
        li[2] = 1.f / lS[pm + 16 + lr];
        li[3] = 1.f / lS[pm + 24 + lr];
        const size_t rowbase = (size_t)(b * S_LEN + qbi * 128);
#pragma unroll
        for (int mt = 0; mt < 2; mt++) {
            size_t r0w = rowbase + pm + mt * 16 + lr;
#pragma unroll
            for (int nt = 0; nt < 8; nt++) {
                int col = h * HDIM + pn + nt * 8 + 2 * lc;
                *(__half2*)(ctx + r0w * D_MODEL + col) =
                    __floats2half2_rn(oacc[mt][nt][0] * li[2 * mt],
                                      oacc[mt][nt][1] * li[2 * mt]);
                *(__half2*)(ctx + (r0w + 8) * D_MODEL + col) =
                    __floats2half2_rn(oacc[mt][nt][2] * li[2 * mt + 1],
                                      oacc[mt][nt][3] * li[2 * mt + 1]);
            }
        }
    }
}

// ---------------------------------------------------------------------------
// Host launch
// ---------------------------------------------------------------------------
extern "C" void kernel_launch(void* const* d_in, const int* in_sizes, int n_in,
                              void* d_out, int out_size) {
    const float* X  = (const float*)d_in[0];
    const float* Wq = (const float*)d_in[3];
    const float* Wk = (const float*)d_in[4];
    const float* Wv = (const float*)d_in[5];
    const float* Wo = (const float*)d_in[6];
    float* out = (float*)d_out;

    __half *pX, *pWT, *pWoT, *pQKV, *pC;
    cudaGetSymbolAddress((void**)&pX,   g_X);
    cudaGetSymbolAddress((void**)&pWT,  g_WT);
    cudaGetSymbolAddress((void**)&pWoT, g_WoT);
    cudaGetSymbolAddress((void**)&pQKV, g_QKV);
    cudaGetSymbolAddress((void**)&pC,   g_ctx);

    cudaFuncSetAttribute(gemm_fp16<__half>, cudaFuncAttributeMaxDynamicSharedMemorySize, GSMEM_BYTES);
    cudaFuncSetAttribute(gemm_fp16<float>,  cudaFuncAttributeMaxDynamicSharedMemorySize, GSMEM_BYTES);
    cudaFuncSetAttribute(attn_fp16, cudaFuncAttributeMaxDynamicSharedMemorySize, ATTN_SMEM);

    static cudaStream_t s1 = nullptr, s2 = nullptr;
    static cudaEvent_t eFork = nullptr, eWqkv = nullptr, eWo = nullptr;
    if (s1 == nullptr) {
        cudaStreamCreateWithFlags(&s1, cudaStreamNonBlocking);
        cudaStreamCreateWithFlags(&s2, cudaStreamNonBlocking);
        cudaEventCreateWithFlags(&eFork, cudaEventDisableTiming);
        cudaEventCreateWithFlags(&eWqkv, cudaEventDisableTiming);
        cudaEventCreateWithFlags(&eWo,   cudaEventDisableTiming);
    }

    // fork
    cudaEventRecord(eFork, 0);
    cudaStreamWaitEvent(s1, eFork, 0);
    cudaStreamWaitEvent(s2, eFork, 0);

    // s1: fused-W transpose (QKV GEMM dep)
    transpose_qkv<<<dim3(NQKV / 32, D_MODEL / 32), dim3(32, 8), 0, s1>>>(Wq, Wk, Wv, pWT);
    cudaEventRecord(eWqkv, s1);

    // s2: Wo transpose (O-proj dep only)
    transpose_wo<<<dim3(D_MODEL / 32, D_MODEL / 32), dim3(32, 8), 0, s2>>>(Wo, pWoT, D_MODEL, D_MODEL);
    cudaEventRecord(eWo, s2);

    // s0: X -> fp16
    cvt_fp16_kernel<<<(BSTOT * D_MODEL / 4) / 256, 256>>>((const float4*)X, (__half2*)pX);

    // fused QKV projection (fp16 out)
    cudaStreamWaitEvent(0, eWqkv, 0);
    gemm_fp16<__half><<<dim3(NQKV / 128, BSTOT / 128), 256, GSMEM_BYTES>>>(pX, pWT, pQKV, NQKV, D_MODEL);

    rope_kernel<<<BSTOT, 128>>>(pQKV);

    attn_fp16<<<dim3(S_LEN / 128, B_SZ * NHEAD), 512, ATTN_SMEM>>>(pQKV, pC);

    // output projection (fp32 out)
    cudaStreamWaitEvent(0, eWo, 0);
    gemm_fp16<float><<<dim3(D_MODEL / 128, BSTOT / 128), 256, GSMEM_BYTES>>>(pC, pWoT, out, D_MODEL, D_MODEL);
}

// round 14
// speedup vs baseline: 1.0492x; 1.0492x over previous
#include <cuda_runtime.h>
#include <cuda_fp16.h>
#include <math.h>
#include <stdint.h>

// Problem constants
#define B_SZ    2
#define S_LEN   2048
#define D_MODEL 2048
#define NHEAD   8
#define HDIM    256
#define BSTOT   (B_SZ * S_LEN)   // 4096
#define NQKV    (D_MODEL + 2 * HDIM)   // 2560
#define QKVP    NQKV

// Scratch (static __device__ arrays — allocation-free rule)
__device__ __half g_X  [(size_t)BSTOT * D_MODEL];
__device__ __half g_WT [(size_t)NQKV * D_MODEL];
__device__ __half g_WoT[(size_t)D_MODEL * D_MODEL];
__device__ __half g_QKV[(size_t)BSTOT * NQKV];
__device__ __half g_ctx[(size_t)BSTOT * D_MODEL];

// ---------------------------------------------------------------------------
// helpers
// ---------------------------------------------------------------------------
__device__ __forceinline__ uint32_t smem_u32(const void* p) {
    uint32_t a;
    asm("{ .reg .u64 t; cvta.to.shared.u64 t, %1; cvt.u32.u64 %0, t; }"
        : "=r"(a) : "l"(p));
    return a;
}

#define CP_ASYNC16(dst, src) \
    asm volatile("cp.async.cg.shared.global [%0], [%1], 16;" :: "r"(dst), "l"(src) : "memory")
#define CP_COMMIT()  asm volatile("cp.async.commit_group;" ::: "memory")
#define CP_WAIT(n)   asm volatile("cp.async.wait_group %0;" :: "n"(n) : "memory")

__device__ __forceinline__ void mma_fp16(float c[4], const uint32_t a[4], const uint32_t b[2]) {
    asm volatile(
        "mma.sync.aligned.m16n8k16.row.col.f32.f16.f16.f32 "
        "{%0,%1,%2,%3}, {%4,%5,%6,%7}, {%8,%9}, {%0,%1,%2,%3};"
        : "+f"(c[0]), "+f"(c[1]), "+f"(c[2]), "+f"(c[3])
        : "r"(a[0]), "r"(a[1]), "r"(a[2]), "r"(a[3]), "r"(b[0]), "r"(b[1]));
}
__device__ __forceinline__ void ldsm4(uint32_t r[4], uint32_t addr) {
    asm volatile("ldmatrix.sync.aligned.m8n8.x4.shared.b16 {%0,%1,%2,%3}, [%4];"
        : "=r"(r[0]), "=r"(r[1]), "=r"(r[2]), "=r"(r[3]) : "r"(addr));
}
__device__ __forceinline__ void ldsm4t(uint32_t r[4], uint32_t addr) {
    asm volatile("ldmatrix.sync.aligned.m8n8.x4.trans.shared.b16 {%0,%1,%2,%3}, [%4];"
        : "=r"(r[0]), "=r"(r[1]), "=r"(r[2]), "=r"(r[3]) : "r"(addr));
}

// output stores (fp16 or fp32 C)
__device__ __forceinline__ void store_pair(__half* C, size_t idx, float a, float b) {
    *(__half2*)(C + idx) = __floats2half2_rn(a, b);
}
__device__ __forceinline__ void store_pair(float* C, size_t idx, float a, float b) {
    *(float2*)(C + idx) = make_float2(a, b);
}

// ---------------------------------------------------------------------------
// fp16 mma.sync GEMM (R11-proven): C[M,N] = A[M,K] @ Bt[N,K]^T
// CTA 128x128, BK=64, 8 warps, warp tile 64x32, 3-stage cp.async + ldmatrix.
// ---------------------------------------------------------------------------
#define GSTAGES 3
#define GP      72                    // smem pitch (halves)
#define TILE_H  (128 * GP)
#define STAGE_B (2 * TILE_H * 2)      // 36,864 B (A+B)
#define GSMEM_BYTES (GSTAGES * STAGE_B)   // 110,592 B

template <typename OutT>
__global__ __launch_bounds__(256, 2) void gemm_fp16(
    const __half* __restrict__ A, const __half* __restrict__ Bt,
    OutT* __restrict__ C, int N, int K)
{
    extern __shared__ __align__(16) char smc[];
    const uint32_t sb = smem_u32(smc);

    const int tid  = threadIdx.x;
    const int wid  = tid >> 5;
    const int lane = tid & 31;
    const int wm   = wid >> 2;
    const int wn   = wid & 3;
    const int lr   = lane >> 2;
    const int lc   = lane & 3;
    const int m0   = blockIdx.y << 7;
    const int n0   = blockIdx.x << 7;
    const int KT   = K >> 6;

    const int t8   = lane >> 3;
    const int trow = lane & 7;
    const uint32_t aOff = (uint32_t)((wm * 64 + (t8 & 1) * 8 + trow) * GP + ((t8 >> 1) << 3)) * 2;
    const uint32_t bOff = (uint32_t)((wn * 32 + (t8 >> 1) * 8 + trow) * GP + ((t8 & 1) << 3)) * 2;

    const __half* Ag = A  + (size_t)m0 * K;
    const __half* Bg = Bt + (size_t)n0 * K;

    float acc[4][4][4];
#pragma unroll
    for (int i = 0; i < 4; i++)
#pragma unroll
        for (int j = 0; j < 4; j++)
#pragma unroll
            for (int v = 0; v < 4; v++) acc[i][j][v] = 0.f;

    auto load_tile = [&](int s, int kt) {
        const __half* ag = Ag + kt * 64;
        const __half* bg = Bg + kt * 64;
        uint32_t sa = sb + (uint32_t)s * STAGE_B;
        uint32_t sbb = sa + TILE_H * 2;
        int idx = tid;
#pragma unroll
        for (int i = 0; i < 4; i++, idx += 256) {
            int row = idx >> 3;
            int c8  = (idx & 7) << 3;
            uint32_t off = (uint32_t)(row * GP + c8) * 2;
            CP_ASYNC16(sa + off,  ag + (size_t)row * K + c8);
            CP_ASYNC16(sbb + off, bg + (size_t)row * K + c8);
        }
    };

#pragma unroll
    for (int s = 0; s < GSTAGES - 1; s++) {
        load_tile(s, s);
        CP_COMMIT();
    }

    for (int kt = 0; kt < KT; kt++) {
        CP_WAIT(GSTAGES - 2);
        __syncthreads();

        if (kt + GSTAGES - 1 < KT) load_tile((kt + GSTAGES - 1) % GSTAGES, kt + GSTAGES - 1);
        CP_COMMIT();

        const uint32_t aBase = sb + (uint32_t)((kt % GSTAGES) * STAGE_B) + aOff;
        const uint32_t bBase = aBase - aOff + TILE_H * 2 + bOff;

#pragma unroll
        for (int kk = 0; kk < 64; kk += 16) {
            uint32_t a[4][4], b[2][4];
            ldsm4(a[0], aBase + (uint32_t)kk * 2);
            ldsm4(b[0], bBase + (uint32_t)kk * 2);
            ldsm4(b[1], bBase + (uint32_t)(16 * GP + kk) * 2);
            ldsm4(a[1], aBase + (uint32_t)(1 * 16 * GP + kk) * 2);
            ldsm4(a[2], aBase + (uint32_t)(2 * 16 * GP + kk) * 2);
            ldsm4(a[3], aBase + (uint32_t)(3 * 16 * GP + kk) * 2);
#pragma unroll
            for (int mt = 0; mt < 4; mt++)
#pragma unroll
                for (int nt = 0; nt < 4; nt++)
                    mma_fp16(acc[mt][nt], a[mt], &b[nt >> 1][(nt & 1) * 2]);
        }
    }

#pragma unroll
    for (int mt = 0; mt < 4; mt++) {
        int r0 = m0 + wm * 64 + mt * 16 + lr;
#pragma unroll
        for (int nt = 0; nt < 4; nt++) {
            int c = n0 + wn * 32 + nt * 8 + lc * 2;
            store_pair(C, (size_t)r0 * N + c,       acc[mt][nt][0], acc[mt][nt][1]);
            store_pair(C, (size_t)(r0 + 8) * N + c, acc[mt][nt][2], acc[mt][nt][3]);
        }
    }
}

// ---------------------------------------------------------------------------
// Prep kernels (fp16 outputs)
// ---------------------------------------------------------------------------
__global__ void transpose_qkv(const float* __restrict__ Wq,
                              const float* __restrict__ Wk,
                              const float* __restrict__ Wv,
                              __half* __restrict__ out) {
    __shared__ float t[32][33];
    int n0 = blockIdx.x * 32;
    int k0 = blockIdx.y * 32;
    int x = threadIdx.x, y = threadIdx.y;  // (32, 8)

    const float* src;
    int scol, pitch;
    if (n0 < D_MODEL)              { src = Wq; scol = n0;                  pitch = D_MODEL; }
    else if (n0 < D_MODEL + HDIM)  { src = Wk; scol = n0 - D_MODEL;        pitch = HDIM; }
    else                           { src = Wv; scol = n0 - D_MODEL - HDIM; pitch = HDIM; }

#pragma unroll
    for (int j = 0; j < 32; j += 8)
        t[y + j][x] = src[(size_t)(k0 + y + j) * pitch + scol + x];
    __syncthreads();
#pragma unroll
    for (int j = 0; j < 32; j += 8)
        out[(size_t)(n0 + y + j) * D_MODEL + k0 + x] = __float2half_rn(t[x][y + j]);
}

__global__ void transpose_wo(const float* __restrict__ in, __half* __restrict__ out,
                             int rows, int cols) {
    __shared__ float t[32][33];
    int c0 = blockIdx.x * 32, r0 = blockIdx.y * 32;
    int x = threadIdx.x, y = threadIdx.y;  // (32, 8)
#pragma unroll
    for (int j = 0; j < 32; j += 8)
        t[y + j][x] = in[(size_t)(r0 + y + j) * cols + c0 + x];
    __syncthreads();
#pragma unroll
    for (int j = 0; j < 32; j += 8)
        out[(size_t)(c0 + y + j) * rows + r0 + x] = __float2half_rn(t[x][y + j]);
}

__global__ void cvt_fp16_kernel(const float4* __restrict__ in, __half2* __restrict__ out) {
    size_t i = (size_t)blockIdx.x * blockDim.x + threadIdx.x;
    float4 v = in[i];
    out[2 * i]     = __floats2half2_rn(v.x, v.y);
    out[2 * i + 1] = __floats2half2_rn(v.z, v.w);
}

// ---------------------------------------------------------------------------
// RoPE in-place on fused fp16 QKV (Q all heads + K slice). 2 rows per block.
// ---------------------------------------------------------------------------
__global__ void rope_kernel(__half* __restrict__ QKV) {
    const int bs  = blockIdx.x * 2 + (threadIdx.x >> 7);
    const int d   = threadIdx.x & 127;
    const int pos = bs & (S_LEN - 1);

    const double inv = exp(-((double)(2 * d) / (double)HDIM) * 9.210340371976184);
    const double ang = (double)pos * inv;
    const double red = ang - 6.283185307179586 * rint(ang * 0.15915494309189535);
    float sn, c;
    sincosf((float)red, &sn, &c);

    __half* row = QKV + (size_t)bs * QKVP;
#pragma unroll
    for (int h = 0; h < NHEAD; h++) {
        float q1 = __half2float(row[h * HDIM + d]);
        float q2 = __half2float(row[h * HDIM + 128 + d]);
        row[h * HDIM + d]       = __float2half_rn(q1 * c - q2 * sn);
        row[h * HDIM + 128 + d] = __float2half_rn(q2 * c + q1 * sn);
    }
    __half* krow = row + D_MODEL;
    float k1 = __half2float(krow[d]), k2 = __half2float(krow[128 + d]);
    krow[d]       = __float2half_rn(k1 * c - k2 * sn);
    krow[128 + d] = __float2half_rn(k2 * c + k1 * sn);
}

// ---------------------------------------------------------------------------
// fp16 tensor-core flash attention (R11 schedule, BM=64, occ 2) with the
// R12-proven ping-pong stats (4 syncs/iter instead of 5):
//   owner writes mS/lS into the other parity slot concurrently with PV;
//   PV threads recompute alpha locally from mS[cur] + pmax.
// ---------------------------------------------------------------------------
#define APH 264   // Q/K/V pitch (halves)
#define PPH 72    // P pitch (halves)
#define ATTN_HALVES (3 * 64 * APH + 64 * PPH)
#define ATTN_SMEM (ATTN_HALVES * 2 + 512 * 4)   // 112,640 B

__global__ __launch_bounds__(256, 2) void attn_fp16(
        const __half* __restrict__ QKV, __half* __restrict__ ctx) {
    extern __shared__ __align__(16) char smc[];
    __half* Qs = (__half*)smc;           // [64][264]
    __half* Ks = Qs + 64 * APH;          // [64][264]
    __half* Vs = Ks + 64 * APH;          // [64][264]  (rows = keys, cols = d)
    __half* Ps = Vs + 64 * APH;          // [64][72]
    float* pmax = (float*)(smc + ATTN_HALVES * 2);  // [2][64] by n-group
    float* psum = pmax + 128;                        // [2][64]
    float* mS   = psum + 128;                        // [2][64] ping-pong
    float* lS   = mS + 128;                          // [2][64] ping-pong

    const uint32_t qs_u = smem_u32(Qs);
    const uint32_t ks_u = smem_u32(Ks);
    const uint32_t vs_u = smem_u32(Vs);
    const uint32_t ps_u = smem_u32(Ps);

    const int qb  = (int)gridDim.x - 1 - (int)blockIdx.x;  // heavy blocks first
    const int b   = blockIdx.y >> 3;
    const int h   = blockIdx.y & 7;
    const int tid = threadIdx.x;
    const int wid = tid >> 5;
    const int lane = tid & 31;
    const int lr  = lane >> 2;
    const int lc  = lane & 3;

    const int smw = (wid & 3) << 4;    // S-phase m
    const int g   = wid >> 2;          // S-phase n group (0/1)
    const int snw = g << 5;
    const int pm  = (wid & 1) << 5;    // PV m
    const int pn  = (wid >> 1) << 6;   // PV n

    const int t8   = lane >> 3;
    const int trow = lane & 7;
    const uint32_t qOff = (uint32_t)((smw + (t8 & 1) * 8 + trow) * APH + ((t8 >> 1) << 3)) * 2;
    const uint32_t kOff = (uint32_t)((snw + (t8 >> 1) * 8 + trow) * APH + ((t8 & 1) << 3)) * 2;
    const uint32_t pOff = (uint32_t)((pm + (t8 & 1) * 8 + trow) * PPH + ((t8 >> 1) << 3)) * 2;
    const uint32_t vOff = (uint32_t)(((t8 & 1) * 8 + trow) * APH + pn + ((t8 >> 1) << 3)) * 2;

    const __half* Kg = QKV + (size_t)b * S_LEN * QKVP + D_MODEL;
    const __half* Vg = Kg + HDIM;
    const float scale = 0.0625f;

    auto load_K = [&](int kb) {
        const __half* kt = Kg + (size_t)kb * 64 * QKVP;
        int idx = tid;
#pragma unroll
        for (int i = 0; i < 8; i++, idx += 256) {
            int row = idx >> 5;
            int c8  = (idx & 31) << 3;
            CP_ASYNC16(ks_u + (uint32_t)(row * APH + c8) * 2,
                       kt + (size_t)row * QKVP + c8);
        }
    };
    auto load_V = [&](int kb) {
        const __half* vt = Vg + (size_t)kb * 64 * QKVP;
        int idx = tid;
#pragma unroll
        for (int i = 0; i < 8; i++, idx += 256) {
            int row = idx >> 5;
            int c8  = (idx & 31) << 3;
            CP_ASYNC16(vs_u + (uint32_t)(row * APH + c8) * 2,
                       vt + (size_t)row * QKVP + c8);
        }
    };

    // prologue: group A = [Q tile + K(0)], group B = [V(0)]
    {
        const __half* Qg = QKV + (size_t)(b * S_LEN + qb * 64) * QKVP + h * HDIM;
        int idx = tid;
#pragma unroll
        for (int i = 0; i < 8; i++, idx += 256) {
            int row = idx >> 5;
            int c8  = (idx & 31) << 3;
            CP_ASYNC16(qs_u + (uint32_t)(row * APH + c8) * 2,
                       Qg + (size_t)row * QKVP + c8);
        }
        load_K(0);
        CP_COMMIT();
        load_V(0);
        CP_COMMIT();
    }
    if (tid < 64) { mS[tid] = -INFINITY; lS[tid] = 0.f; }  // parity slot 0

    float oacc[2][8][4];
#pragma unroll
    for (int mt = 0; mt < 2; mt++)
#pragma unroll
        for (int nt = 0; nt < 8; nt++)
#pragma unroll
            for (int v = 0; v < 4; v++) oacc[mt][nt][v] = 0.f;

    for (int kb = 0; kb <= qb; kb++) {
        const int cur = (kb & 1) * 64;
        const int nxt = cur ^ 64;

        CP_WAIT(1);          // K(kb) ready; V(kb) may still be in flight
        __syncthreads();

        // ---- S = Q K^T (fp16 k16) ----
        float sacc[4][4];
#pragma unroll
        for (int nt = 0; nt < 4; nt++)
#pragma unroll
            for (int v = 0; v < 4; v++) sacc[nt][v] = 0.f;

#pragma unroll 4
        for (int k = 0; k < HDIM; k += 16) {
            uint32_t af[4], bf[2][4];
            ldsm4(af, qs_u + qOff + (uint32_t)k * 2);
            ldsm4(bf[0], ks_u + kOff + (uint32_t)k * 2);
            ldsm4(bf[1], ks_u + kOff + (uint32_t)(16 * APH + k) * 2);
#pragma unroll
            for (int nt = 0; nt < 4; nt++)
                mma_fp16(sacc[nt], af, &bf[nt >> 1][(nt & 1) * 2]);
        }

        // ---- scale + mask (fp32 regs) ----
        const bool diag = (kb == qb);
        const int r0 = smw + lr, r1 = r0 + 8;
#pragma unroll
        for (int nt = 0; nt < 4; nt++) {
            int c0 = snw + nt * 8 + 2 * lc;
            sacc[nt][0] *= scale; sacc[nt][1] *= scale;
            sacc[nt][2] *= scale; sacc[nt][3] *= scale;
            if (diag) {
                if (c0 > r0)     sacc[nt][0] = -INFINITY;
                if (c0 + 1 > r0) sacc[nt][1] = -INFINITY;
                if (c0 > r1)     sacc[nt][2] = -INFINITY;
                if (c0 + 1 > r1) sacc[nt][3] = -INFINITY;
            }
        }

        // ---- row-max partials ----
        float m0p = -INFINITY, m1p = -INFINITY;
#pragma unroll
        for (int nt = 0; nt < 4; nt++) {
            m0p = fmaxf(m0p, fmaxf(sacc[nt][0], sacc[nt][1]));
            m1p = fmaxf(m1p, fmaxf(sacc[nt][2], sacc[nt][3]));
        }
        m0p = fmaxf(m0p, __shfl_xor_sync(0xffffffffu, m0p, 1));
        m0p = fmaxf(m0p, __shfl_xor_sync(0xffffffffu, m0p, 2));
        m1p = fmaxf(m1p, __shfl_xor_sync(0xffffffffu, m1p, 1));
        m1p = fmaxf(m1p, __shfl_xor_sync(0xffffffffu, m1p, 2));
        if (lc == 0) { pmax[g * 64 + r0] = m0p; pmax[g * 64 + r1] = m1p; }
        __syncthreads();   // pmax visible; Ks fully consumed

        if (kb < qb) load_K(kb + 1);   // overlaps softmax + PV
        CP_COMMIT();

        // ---- exp on regs, fp16 P, partial sums ----
        float mnew0 = fmaxf(mS[cur + r0], fmaxf(pmax[r0], pmax[64 + r0]));
        float mnew1 = fmaxf(mS[cur + r1], fmaxf(pmax[r1], pmax[64 + r1]));
        float s0 = 0.f, s1 = 0.f;
#pragma unroll
        for (int nt = 0; nt < 4; nt++) {
            int c0 = snw + nt * 8 + 2 * lc;
            float p0 = __expf(sacc[nt][0] - mnew0);
            float p1 = __expf(sacc[nt][1] - mnew0);
            float p2 = __expf(sacc[nt][2] - mnew1);
            float p3 = __expf(sacc[nt][3] - mnew1);
            s0 += p0 + p1; s1 += p2 + p3;
            *(__half2*)(Ps + r0 * PPH + c0) = __floats2half2_rn(p0, p1);
            *(__half2*)(Ps + r1 * PPH + c0) = __floats2half2_rn(p2, p3);
        }
        s0 += __shfl_xor_sync(0xffffffffu, s0, 1);
        s0 += __shfl_xor_sync(0xffffffffu, s0, 2);
        s1 += __shfl_xor_sync(0xffffffffu, s1, 1);
        s1 += __shfl_xor_sync(0xffffffffu, s1, 2);
        if (lc == 0) { psum[g * 64 + r0] = s0; psum[g * 64 + r1] = s1; }

        CP_WAIT(1);          // V(kb) ready; K(kb+1) stays in flight
        __syncthreads();     // psum/pmax/Ps visible; Vs ready

        // ---- owner updates stats into the OTHER parity slot (during PV) ----
        if (g == 0 && lc == 0) {
            float a0 = __expf(mS[cur + r0] - mnew0);
            float a1 = __expf(mS[cur + r1] - mnew1);
            lS[nxt + r0] = lS[cur + r0] * a0 + psum[r0] + psum[64 + r0];
            lS[nxt + r1] = lS[cur + r1] * a1 + psum[r1] + psum[64 + r1];
            mS[nxt + r0] = mnew0;
            mS[nxt + r1] = mnew1;
        }

        // ---- O rescale with locally recomputed alphas + PV ----
        {
            float al[4];
#pragma unroll
            for (int i = 0; i < 4; i++) {
                int r = pm + i * 8 + lr;
                float mo = mS[cur + r];
                float mn = fmaxf(mo, fmaxf(pmax[r], pmax[64 + r]));
                al[i] = __expf(mo - mn);
            }
#pragma unroll
            for (int nt = 0; nt < 8; nt++) {
                oacc[0][nt][0] *= al[0]; oacc[0][nt][1] *= al[0];
                oacc[0][nt][2] *= al[1]; oacc[0][nt][3] *= al[1];
                oacc[1][nt][0] *= al[2]; oacc[1][nt][1] *= al[2];
                oacc[1][nt][2] *= al[3]; oacc[1][nt][3] *= al[3];
            }
#pragma unroll
            for (int k = 0; k < 64; k += 16) {
                uint32_t aP0[4], aP1[4], bv[4][4];
                ldsm4(aP0, ps_u + pOff + (uint32_t)k * 2);
                ldsm4(aP1, ps_u + pOff + (uint32_t)(16 * PPH + k) * 2);
#pragma unroll
                for (int nn = 0; nn < 4; nn++)
                    ldsm4t(bv[nn], vs_u + vOff + (uint32_t)(k * APH + nn * 16) * 2);
#pragma unroll
                for (int nt = 0; nt < 8; nt++) {
                    mma_fp16(oacc[0][nt], aP0, &bv[nt >> 1][(nt & 1) * 2]);
                    mma_fp16(oacc[1][nt], aP1, &bv[nt >> 1][(nt & 1) * 2]);
                }
            }
        }
        __syncthreads();   // Vs reads done; stats writes ordered before next iter

        if (kb < qb) load_V(kb + 1);   // overlaps next S + softmax
        CP_COMMIT();
    }

    __syncthreads();   // final-parity stats visible to all

    // ---- normalize + write ctx (fp16) ----
    {
        const int fin = ((qb + 1) & 1) * 64;
        float li[4];
        li[0] = 1.f / lS[fin + pm + lr];
        li[1] = 1.f / lS[fin + pm + lr + 8];
        li[2] = 1.f / lS[fin + pm + 16 + lr];
        li[3] = 1.f / lS[fin + pm + 24 + lr];
        const size_t rowbase = (size_t)(b * S_LEN + qb * 64);
#pragma unroll
        for (int mt = 0; mt < 2; mt++) {
            size_t r0w = rowbase + pm + mt * 16 + lr;
#pragma unroll
            for (int nt = 0; nt < 8; nt++) {
                int col = h * HDIM + pn + nt * 8 + 2 * lc;
                *(__half2*)(ctx + r0w * D_MODEL + col) =
                    __floats2half2_rn(oacc[mt][nt][0] * li[2 * mt],
                                      oacc[mt][nt][1] * li[2 * mt]);
                *(__half2*)(ctx + (r0w + 8) * D_MODEL + col) =
                    __floats2half2_rn(oacc[mt][nt][2] * li[2 * mt + 1],
                                      oacc[mt][nt][3] * li[2 * mt + 1]);
            }
        }
    }
}

// ---------------------------------------------------------------------------
// Host launch (R11 graph shape)
// ---------------------------------------------------------------------------
extern "C" void kernel_launch(void* const* d_in, const int* in_sizes, int n_in,
                              void* d_out, int out_size) {
    const float* X  = (const float*)d_in[0];
    const float* Wq = (const float*)d_in[3];
    const float* Wk = (const float*)d_in[4];
    const float* Wv = (const float*)d_in[5];
    const float* Wo = (const float*)d_in[6];
    float* out = (float*)d_out;

    __half *pX, *pWT, *pWoT, *pQKV, *pC;
    cudaGetSymbolAddress((void**)&pX,   g_X);
    cudaGetSymbolAddress((void**)&pWT,  g_WT);
    cudaGetSymbolAddress((void**)&pWoT, g_WoT);
    cudaGetSymbolAddress((void**)&pQKV, g_QKV);
    cudaGetSymbolAddress((void**)&pC,   g_ctx);

    cudaFuncSetAttribute(gemm_fp16<__half>, cudaFuncAttributeMaxDynamicSharedMemorySize, GSMEM_BYTES);
    cudaFuncSetAttribute(gemm_fp16<float>,  cudaFuncAttributeMaxDynamicSharedMemorySize, GSMEM_BYTES);
    cudaFuncSetAttribute(attn_fp16, cudaFuncAttributeMaxDynamicSharedMemorySize, ATTN_SMEM);

    static cudaStream_t s1 = nullptr, s2 = nullptr;
    static cudaEvent_t eFork = nullptr, eWqkv = nullptr, eWo = nullptr;
    if (s1 == nullptr) {
        cudaStreamCreateWithFlags(&s1, cudaStreamNonBlocking);
        cudaStreamCreateWithFlags(&s2, cudaStreamNonBlocking);
        cudaEventCreateWithFlags(&eFork, cudaEventDisableTiming);
        cudaEventCreateWithFlags(&eWqkv, cudaEventDisableTiming);
        cudaEventCreateWithFlags(&eWo,   cudaEventDisableTiming);
    }

    // fork
    cudaEventRecord(eFork, 0);
    cudaStreamWaitEvent(s1, eFork, 0);
    cudaStreamWaitEvent(s2, eFork, 0);

    // s1: fused-W transpose (QKV GEMM dep)
    transpose_qkv<<<dim3(NQKV / 32, D_MODEL / 32), dim3(32, 8), 0, s1>>>(Wq, Wk, Wv, pWT);
    cudaEventRecord(eWqkv, s1);

    // s2: Wo transpose (O-proj dep only)
    transpose_wo<<<dim3(D_MODEL / 32, D_MODEL / 32), dim3(32, 8), 0, s2>>>(Wo, pWoT, D_MODEL, D_MODEL);
    cudaEventRecord(eWo, s2);

    // s0: X -> fp16
    cvt_fp16_kernel<<<(BSTOT * D_MODEL / 4) / 256, 256>>>((const float4*)X, (__half2*)pX);

    // fused QKV projection (fp16 out)
    cudaStreamWaitEvent(0, eWqkv, 0);
    gemm_fp16<__half><<<dim3(NQKV / 128, BSTOT / 128), 256, GSMEM_BYTES>>>(pX, pWT, pQKV, NQKV, D_MODEL);

    rope_kernel<<<BSTOT / 2, 256>>>(pQKV);

    attn_fp16<<<dim3(S_LEN / 64, B_SZ * NHEAD), 256, ATTN_SMEM>>>(pQKV, pC);

    // output projection (fp32 out)
    cudaStreamWaitEvent(0, eWo, 0);
    gemm_fp16<float><<<dim3(D_MODEL / 128, BSTOT / 128), 256, GSMEM_BYTES>>>(pC, pWoT, out, D_MODEL, D_MODEL);
}

// round 15
// speedup vs baseline: 1.0810x; 1.0303x over previous
#include <cuda_runtime.h>
#include <cuda_fp16.h>
#include <math.h>
#include <stdint.h>

// Problem constants
#define B_SZ    2
#define S_LEN   2048
#define D_MODEL 2048
#define NHEAD   8
#define HDIM    256
#define BSTOT   (B_SZ * S_LEN)   // 4096
#define NQKV    (D_MODEL + 2 * HDIM)   // 2560
#define QKVP    NQKV

// Scratch (static __device__ arrays — allocation-free rule)
__device__ __half g_X  [(size_t)BSTOT * D_MODEL];
__device__ __half g_WT [(size_t)NQKV * D_MODEL];
__device__ __half g_WoT[(size_t)D_MODEL * D_MODEL];
__device__ __half g_QKV[(size_t)BSTOT * NQKV];
__device__ __half g_ctx[(size_t)BSTOT * D_MODEL];

// ---------------------------------------------------------------------------
// helpers
// ---------------------------------------------------------------------------
__device__ __forceinline__ uint32_t smem_u32(const void* p) {
    uint32_t a;
    asm("{ .reg .u64 t; cvta.to.shared.u64 t, %1; cvt.u32.u64 %0, t; }"
        : "=r"(a) : "l"(p));
    return a;
}

#define CP_ASYNC16(dst, src) \
    asm volatile("cp.async.cg.shared.global [%0], [%1], 16;" :: "r"(dst), "l"(src) : "memory")
#define CP_COMMIT()  asm volatile("cp.async.commit_group;" ::: "memory")
#define CP_WAIT(n)   asm volatile("cp.async.wait_group %0;" :: "n"(n) : "memory")

__device__ __forceinline__ void mma_fp16(float c[4], const uint32_t a[4], const uint32_t b[2]) {
    asm volatile(
        "mma.sync.aligned.m16n8k16.row.col.f32.f16.f16.f32 "
        "{%0,%1,%2,%3}, {%4,%5,%6,%7}, {%8,%9}, {%0,%1,%2,%3};"
        : "+f"(c[0]), "+f"(c[1]), "+f"(c[2]), "+f"(c[3])
        : "r"(a[0]), "r"(a[1]), "r"(a[2]), "r"(a[3]), "r"(b[0]), "r"(b[1]));
}
__device__ __forceinline__ void ldsm4(uint32_t r[4], uint32_t addr) {
    asm volatile("ldmatrix.sync.aligned.m8n8.x4.shared.b16 {%0,%1,%2,%3}, [%4];"
        : "=r"(r[0]), "=r"(r[1]), "=r"(r[2]), "=r"(r[3]) : "r"(addr));
}
__device__ __forceinline__ void ldsm4t(uint32_t r[4], uint32_t addr) {
    asm volatile("ldmatrix.sync.aligned.m8n8.x4.trans.shared.b16 {%0,%1,%2,%3}, [%4];"
        : "=r"(r[0]), "=r"(r[1]), "=r"(r[2]), "=r"(r[3]) : "r"(addr));
}

// output stores (fp16 or fp32 C)
__device__ __forceinline__ void store_pair(__half* C, size_t idx, float a, float b) {
    *(__half2*)(C + idx) = __floats2half2_rn(a, b);
}
__device__ __forceinline__ void store_pair(float* C, size_t idx, float a, float b) {
    *(float2*)(C + idx) = make_float2(a, b);
}

// ---------------------------------------------------------------------------
// fp16 mma.sync GEMM (R11-proven): C[M,N] = A[M,K] @ Bt[N,K]^T
// CTA 128x128, BK=64, 8 warps, warp tile 64x32, 3-stage cp.async + ldmatrix.
// ---------------------------------------------------------------------------
#define GSTAGES 3
#define GP      72                    // smem pitch (halves)
#define TILE_H  (128 * GP)
#define STAGE_B (2 * TILE_H * 2)      // 36,864 B (A+B)
#define GSMEM_BYTES (GSTAGES * STAGE_B)   // 110,592 B

template <typename OutT>
__global__ __launch_bounds__(256, 2) void gemm_fp16(
    const __half* __restrict__ A, const __half* __restrict__ Bt,
    OutT* __restrict__ C, int N, int K)
{
    extern __shared__ __align__(16) char smc[];
    const uint32_t sb = smem_u32(smc);

    const int tid  = threadIdx.x;
    const int wid  = tid >> 5;
    const int lane = tid & 31;
    const int wm   = wid >> 2;
    const int wn   = wid & 3;
    const int lr   = lane >> 2;
    const int lc   = lane & 3;
    const int m0   = blockIdx.y << 7;
    const int n0   = blockIdx.x << 7;
    const int KT   = K >> 6;

    const int t8   = lane >> 3;
    const int trow = lane & 7;
    const uint32_t aOff = (uint32_t)((wm * 64 + (t8 & 1) * 8 + trow) * GP + ((t8 >> 1) << 3)) * 2;
    const uint32_t bOff = (uint32_t)((wn * 32 + (t8 >> 1) * 8 + trow) * GP + ((t8 & 1) << 3)) * 2;

    const __half* Ag = A  + (size_t)m0 * K;
    const __half* Bg = Bt + (size_t)n0 * K;

    float acc[4][4][4];
#pragma unroll
    for (int i = 0; i < 4; i++)
#pragma unroll
        for (int j = 0; j < 4; j++)
#pragma unroll
            for (int v = 0; v < 4; v++) acc[i][j][v] = 0.f;

    auto load_tile = [&](int s, int kt) {
        const __half* ag = Ag + kt * 64;
        const __half* bg = Bg + kt * 64;
        uint32_t sa = sb + (uint32_t)s * STAGE_B;
        uint32_t sbb = sa + TILE_H * 2;
        int idx = tid;
#pragma unroll
        for (int i = 0; i < 4; i++, idx += 256) {
            int row = idx >> 3;
            int c8  = (idx & 7) << 3;
            uint32_t off = (uint32_t)(row * GP + c8) * 2;
            CP_ASYNC16(sa + off,  ag + (size_t)row * K + c8);
            CP_ASYNC16(sbb + off, bg + (size_t)row * K + c8);
        }
    };

#pragma unroll
    for (int s = 0; s < GSTAGES - 1; s++) {
        load_tile(s, s);
        CP_COMMIT();
    }

    for (int kt = 0; kt < KT; kt++) {
        CP_WAIT(GSTAGES - 2);
        __syncthreads();

        if (kt + GSTAGES - 1 < KT) load_tile((kt + GSTAGES - 1) % GSTAGES, kt + GSTAGES - 1);
        CP_COMMIT();

        const uint32_t aBase = sb + (uint32_t)((kt % GSTAGES) * STAGE_B) + aOff;
        const uint32_t bBase = aBase - aOff + TILE_H * 2 + bOff;

#pragma unroll
        for (int kk = 0; kk < 64; kk += 16) {
            uint32_t a[4][4], b[2][4];
            ldsm4(a[0], aBase + (uint32_t)kk * 2);
            ldsm4(b[0], bBase + (uint32_t)kk * 2);
            ldsm4(b[1], bBase + (uint32_t)(16 * GP + kk) * 2);
            ldsm4(a[1], aBase + (uint32_t)(1 * 16 * GP + kk) * 2);
            ldsm4(a[2], aBase + (uint32_t)(2 * 16 * GP + kk) * 2);
            ldsm4(a[3], aBase + (uint32_t)(3 * 16 * GP + kk) * 2);
#pragma unroll
            for (int mt = 0; mt < 4; mt++)
#pragma unroll
                for (int nt = 0; nt < 4; nt++)
                    mma_fp16(acc[mt][nt], a[mt], &b[nt >> 1][(nt & 1) * 2]);
        }
    }

#pragma unroll
    for (int mt = 0; mt < 4; mt++) {
        int r0 = m0 + wm * 64 + mt * 16 + lr;
#pragma unroll
        for (int nt = 0; nt < 4; nt++) {
            int c = n0 + wn * 32 + nt * 8 + lc * 2;
            store_pair(C, (size_t)r0 * N + c,       acc[mt][nt][0], acc[mt][nt][1]);
            store_pair(C, (size_t)(r0 + 8) * N + c, acc[mt][nt][2], acc[mt][nt][3]);
        }
    }
}

// ---------------------------------------------------------------------------
// Prep kernels (fp16 outputs)
// ---------------------------------------------------------------------------
__global__ void transpose_qkv(const float* __restrict__ Wq,
                              const float* __restrict__ Wk,
                              const float* __restrict__ Wv,
                              __half* __restrict__ out) {
    __shared__ float t[32][33];
    int n0 = blockIdx.x * 32;
    int k0 = blockIdx.y * 32;
    int x = threadIdx.x, y = threadIdx.y;  // (32, 8)

    const float* src;
    int scol, pitch;
    if (n0 < D_MODEL)              { src = Wq; scol = n0;                  pitch = D_MODEL; }
    else if (n0 < D_MODEL + HDIM)  { src = Wk; scol = n0 - D_MODEL;        pitch = HDIM; }
    else                           { src = Wv; scol = n0 - D_MODEL - HDIM; pitch = HDIM; }

#pragma unroll
    for (int j = 0; j < 32; j += 8)
        t[y + j][x] = src[(size_t)(k0 + y + j) * pitch + scol + x];
    __syncthreads();
#pragma unroll
    for (int j = 0; j < 32; j += 8)
        out[(size_t)(n0 + y + j) * D_MODEL + k0 + x] = __float2half_rn(t[x][y + j]);
}

__global__ void transpose_wo(const float* __restrict__ in, __half* __restrict__ out,
                             int rows, int cols) {
    __shared__ float t[32][33];
    int c0 = blockIdx.x * 32, r0 = blockIdx.y * 32;
    int x = threadIdx.x, y = threadIdx.y;  // (32, 8)
#pragma unroll
    for (int j = 0; j < 32; j += 8)
        t[y + j][x] = in[(size_t)(r0 + y + j) * cols + c0 + x];
    __syncthreads();
#pragma unroll
    for (int j = 0; j < 32; j += 8)
        out[(size_t)(c0 + y + j) * rows + r0 + x] = __float2half_rn(t[x][y + j]);
}

__global__ void cvt_fp16_kernel(const float4* __restrict__ in, __half2* __restrict__ out) {
    size_t i = (size_t)blockIdx.x * blockDim.x + threadIdx.x;
    float4 v = in[i];
    out[2 * i]     = __floats2half2_rn(v.x, v.y);
    out[2 * i + 1] = __floats2half2_rn(v.z, v.w);
}

// ---------------------------------------------------------------------------
// RoPE in-place on fused fp16 QKV (Q all heads + K slice). R11 config.
// ---------------------------------------------------------------------------
__global__ void rope_kernel(__half* __restrict__ QKV) {
    const int bs  = blockIdx.x;
    const int d   = threadIdx.x;          // 0..127
    const int pos = bs & (S_LEN - 1);

    const double inv = exp(-((double)(2 * d) / (double)HDIM) * 9.210340371976184);
    const double ang = (double)pos * inv;
    const double red = ang - 6.283185307179586 * rint(ang * 0.15915494309189535);
    float sn, c;
    sincosf((float)red, &sn, &c);

    __half* row = QKV + (size_t)bs * QKVP;
#pragma unroll
    for (int h = 0; h < NHEAD; h++) {
        float q1 = __half2float(row[h * HDIM + d]);
        float q2 = __half2float(row[h * HDIM + 128 + d]);
        row[h * HDIM + d]       = __float2half_rn(q1 * c - q2 * sn);
        row[h * HDIM + 128 + d] = __float2half_rn(q2 * c + q1 * sn);
    }
    __half* krow = row + D_MODEL;
    float k1 = __half2float(krow[d]), k2 = __half2float(krow[128 + d]);
    krow[d]       = __float2half_rn(k1 * c - k2 * sn);
    krow[128 + d] = __float2half_rn(k2 * c + k1 * sn);
}

// ---------------------------------------------------------------------------
// fp16 tensor-core flash attention — EXACT R11 schedule (best known), plus
// smem-staged coalesced ctx epilogue (reuses dead Qs buffer; 16B row chunks).
// ---------------------------------------------------------------------------
#define APH 264   // Q/K/V pitch (halves)
#define PPH 72    // P pitch (halves)
#define ATTN_HALVES (3 * 64 * APH + 64 * PPH)
#define ATTN_SMEM (ATTN_HALVES * 2 + 448 * 4)   // 112,384 B

__global__ __launch_bounds__(256, 2) void attn_fp16(
        const __half* __restrict__ QKV, __half* __restrict__ ctx) {
    extern __shared__ __align__(16) char smc[];
    __half* Qs = (__half*)smc;           // [64][264]
    __half* Ks = Qs + 64 * APH;          // [64][264]
    __half* Vs = Ks + 64 * APH;          // [64][264]  (rows = keys, cols = d)
    __half* Ps = Vs + 64 * APH;          // [64][72]
    float* pmax = (float*)(smc + ATTN_HALVES * 2);  // [2][64] by n-group
    float* psum = pmax + 128;                        // [2][64]
    float* mS   = psum + 128;
    float* lS   = mS + 64;
    float* aS   = lS + 64;

    const uint32_t qs_u = smem_u32(Qs);
    const uint32_t ks_u = smem_u32(Ks);
    const uint32_t vs_u = smem_u32(Vs);
    const uint32_t ps_u = smem_u32(Ps);

    const int qb  = (int)gridDim.x - 1 - (int)blockIdx.x;  // heavy blocks first
    const int b   = blockIdx.y >> 3;
    const int h   = blockIdx.y & 7;
    const int tid = threadIdx.x;
    const int wid = tid >> 5;
    const int lane = tid & 31;
    const int lr  = lane >> 2;
    const int lc  = lane & 3;

    const int smw = (wid & 3) << 4;    // S-phase m
    const int g   = wid >> 2;          // S-phase n group (0/1)
    const int snw = g << 5;
    const int pm  = (wid & 1) << 5;    // PV m
    const int pn  = (wid >> 1) << 6;   // PV n

    const int t8   = lane >> 3;
    const int trow = lane & 7;
    const uint32_t qOff = (uint32_t)((smw + (t8 & 1) * 8 + trow) * APH + ((t8 >> 1) << 3)) * 2;
    const uint32_t kOff = (uint32_t)((snw + (t8 >> 1) * 8 + trow) * APH + ((t8 & 1) << 3)) * 2;
    const uint32_t pOff = (uint32_t)((pm + (t8 & 1) * 8 + trow) * PPH + ((t8 >> 1) << 3)) * 2;
    const uint32_t vOff = (uint32_t)(((t8 & 1) * 8 + trow) * APH + pn + ((t8 >> 1) << 3)) * 2;

    const __half* Kg = QKV + (size_t)b * S_LEN * QKVP + D_MODEL;
    const __half* Vg = Kg + HDIM;
    const float scale = 0.0625f;

    auto load_K = [&](int kb) {
        const __half* kt = Kg + (size_t)kb * 64 * QKVP;
        int idx = tid;
#pragma unroll
        for (int i = 0; i < 8; i++, idx += 256) {
            int row = idx >> 5;
            int c8  = (idx & 31) << 3;
            CP_ASYNC16(ks_u + (uint32_t)(row * APH + c8) * 2,
                       kt + (size_t)row * QKVP + c8);
        }
    };
    auto load_V = [&](int kb) {
        const __half* vt = Vg + (size_t)kb * 64 * QKVP;
        int idx = tid;
#pragma unroll
        for (int i = 0; i < 8; i++, idx += 256) {
            int row = idx >> 5;
            int c8  = (idx & 31) << 3;
            CP_ASYNC16(vs_u + (uint32_t)(row * APH + c8) * 2,
                       vt + (size_t)row * QKVP + c8);
        }
    };

    // prologue: group A = [Q tile + K(0)], group B = [V(0)]
    {
        const __half* Qg = QKV + (size_t)(b * S_LEN + qb * 64) * QKVP + h * HDIM;
        int idx = tid;
#pragma unroll
        for (int i = 0; i < 8; i++, idx += 256) {
            int row = idx >> 5;
            int c8  = (idx & 31) << 3;
            CP_ASYNC16(qs_u + (uint32_t)(row * APH + c8) * 2,
                       Qg + (size_t)row * QKVP + c8);
        }
        load_K(0);
        CP_COMMIT();
        load_V(0);
        CP_COMMIT();
    }
    if (tid < 64) { mS[tid] = -INFINITY; lS[tid] = 0.f; }

    float oacc[2][8][4];
#pragma unroll
    for (int mt = 0; mt < 2; mt++)
#pragma unroll
        for (int nt = 0; nt < 8; nt++)
#pragma unroll
            for (int v = 0; v < 4; v++) oacc[mt][nt][v] = 0.f;

    for (int kb = 0; kb <= qb; kb++) {
        CP_WAIT(1);          // K(kb) ready; V(kb) may still be in flight
        __syncthreads();

        // ---- S = Q K^T (fp16 k16) ----
        float sacc[4][4];
#pragma unroll
        for (int nt = 0; nt < 4; nt++)
#pragma unroll
            for (int v = 0; v < 4; v++) sacc[nt][v] = 0.f;

#pragma unroll 4
        for (int k = 0; k < HDIM; k += 16) {
            uint32_t af[4], bf[2][4];
            ldsm4(af, qs_u + qOff + (uint32_t)k * 2);
            ldsm4(bf[0], ks_u + kOff + (uint32_t)k * 2);
            ldsm4(bf[1], ks_u + kOff + (uint32_t)(16 * APH + k) * 2);
#pragma unroll
            for (int nt = 0; nt < 4; nt++)
                mma_fp16(sacc[nt], af, &bf[nt >> 1][(nt & 1) * 2]);
        }

        // ---- scale + mask in fp32 registers ----
        const bool diag = (kb == qb);
        const int r0 = smw + lr, r1 = r0 + 8;
#pragma unroll
        for (int nt = 0; nt < 4; nt++) {
            int c0 = snw + nt * 8 + 2 * lc;
            sacc[nt][0] *= scale; sacc[nt][1] *= scale;
            sacc[nt][2] *= scale; sacc[nt][3] *= scale;
            if (diag) {
                if (c0 > r0)     sacc[nt][0] = -INFINITY;
                if (c0 + 1 > r0) sacc[nt][1] = -INFINITY;
                if (c0 > r1)     sacc[nt][2] = -INFINITY;
                if (c0 + 1 > r1) sacc[nt][3] = -INFINITY;
            }
        }

        // ---- row-max partials (registers + lc shuffles) ----
        float m0p = -INFINITY, m1p = -INFINITY;
#pragma unroll
        for (int nt = 0; nt < 4; nt++) {
            m0p = fmaxf(m0p, fmaxf(sacc[nt][0], sacc[nt][1]));
            m1p = fmaxf(m1p, fmaxf(sacc[nt][2], sacc[nt][3]));
        }
        m0p = fmaxf(m0p, __shfl_xor_sync(0xffffffffu, m0p, 1));
        m0p = fmaxf(m0p, __shfl_xor_sync(0xffffffffu, m0p, 2));
        m1p = fmaxf(m1p, __shfl_xor_sync(0xffffffffu, m1p, 1));
        m1p = fmaxf(m1p, __shfl_xor_sync(0xffffffffu, m1p, 2));
        if (lc == 0) { pmax[g * 64 + r0] = m0p; pmax[g * 64 + r1] = m1p; }
        __syncthreads();   // pmax visible; Ks fully consumed

        if (kb < qb) load_K(kb + 1);   // overlaps softmax + PV
        CP_COMMIT();

        // ---- exp on registers, fp16 P, partial sums ----
        float mnew0 = fmaxf(mS[r0], fmaxf(pmax[r0], pmax[64 + r0]));
        float mnew1 = fmaxf(mS[r1], fmaxf(pmax[r1], pmax[64 + r1]));
        float s0 = 0.f, s1 = 0.f;
#pragma unroll
        for (int nt = 0; nt < 4; nt++) {
            int c0 = snw + nt * 8 + 2 * lc;
            float p0 = __expf(sacc[nt][0] - mnew0);
            float p1 = __expf(sacc[nt][1] - mnew0);
            float p2 = __expf(sacc[nt][2] - mnew1);
            float p3 = __expf(sacc[nt][3] - mnew1);
            s0 += p0 + p1; s1 += p2 + p3;
            *(__half2*)(Ps + r0 * PPH + c0) = __floats2half2_rn(p0, p1);
            *(__half2*)(Ps + r1 * PPH + c0) = __floats2half2_rn(p2, p3);
        }
        s0 += __shfl_xor_sync(0xffffffffu, s0, 1);
        s0 += __shfl_xor_sync(0xffffffffu, s0, 2);
        s1 += __shfl_xor_sync(0xffffffffu, s1, 1);
        s1 += __shfl_xor_sync(0xffffffffu, s1, 2);
        if (lc == 0) { psum[g * 64 + r0] = s0; psum[g * 64 + r1] = s1; }

        CP_WAIT(1);          // V(kb) ready; K(kb+1) stays in flight
        __syncthreads();     // psum/Ps visible; Vs ready

        // ---- single-writer stats update ----
        if (g == 0 && lc == 0) {
            float a0 = __expf(mS[r0] - mnew0);
            float a1 = __expf(mS[r1] - mnew1);
            lS[r0] = lS[r0] * a0 + psum[r0] + psum[64 + r0];
            lS[r1] = lS[r1] * a1 + psum[r1] + psum[64 + r1];
            mS[r0] = mnew0; mS[r1] = mnew1;
            aS[r0] = a0;    aS[r1] = a1;
        }
        __syncthreads();     // aS/lS visible

        // ---- O rescale + O += P @ V (V B-frags via ldmatrix.trans) ----
        {
            float a00 = aS[pm + lr];
            float a01 = aS[pm + lr + 8];
            float a10 = aS[pm + 16 + lr];
            float a11 = aS[pm + 24 + lr];
#pragma unroll
            for (int nt = 0; nt < 8; nt++) {
                oacc[0][nt][0] *= a00; oacc[0][nt][1] *= a00;
                oacc[0][nt][2] *= a01; oacc[0][nt][3] *= a01;
                oacc[1][nt][0] *= a10; oacc[1][nt][1] *= a10;
                oacc[1][nt][2] *= a11; oacc[1][nt][3] *= a11;
            }
#pragma unroll
            for (int k = 0; k < 64; k += 16) {
                uint32_t aP0[4], aP1[4], bv[4][4];
                ldsm4(aP0, ps_u + pOff + (uint32_t)k * 2);
                ldsm4(aP1, ps_u + pOff + (uint32_t)(16 * PPH + k) * 2);
#pragma unroll
                for (int nn = 0; nn < 4; nn++)
                    ldsm4t(bv[nn], vs_u + vOff + (uint32_t)(k * APH + nn * 16) * 2);
#pragma unroll
                for (int nt = 0; nt < 8; nt++) {
                    mma_fp16(oacc[0][nt], aP0, &bv[nt >> 1][(nt & 1) * 2]);
                    mma_fp16(oacc[1][nt], aP1, &bv[nt >> 1][(nt & 1) * 2]);
                }
            }
        }
        __syncthreads();   // Vs reads done

        if (kb < qb) load_V(kb + 1);   // overlaps next S + softmax
        CP_COMMIT();
    }

    // ---- epilogue: stage normalized O in Qs (dead), then coalesced write ----
    {
        float li[4];
        li[0] = 1.f / lS[pm + lr];
        li[1] = 1.f / lS[pm + lr + 8];
        li[2] = 1.f / lS[pm + 16 + lr];
        li[3] = 1.f / lS[pm + 24 + lr];
#pragma unroll
        for (int mt = 0; mt < 2; mt++) {
            int rr = pm + mt * 16 + lr;
#pragma unroll
            for (int nt = 0; nt < 8; nt++) {
                int col = pn + nt * 8 + 2 * lc;
                *(__half2*)(Qs + rr * APH + col) =
                    __floats2half2_rn(oacc[mt][nt][0] * li[2 * mt],
                                      oacc[mt][nt][1] * li[2 * mt]);
                *(__half2*)(Qs + (rr + 8) * APH + col) =
                    __floats2half2_rn(oacc[mt][nt][2] * li[2 * mt + 1],
                                      oacc[mt][nt][3] * li[2 * mt + 1]);
            }
        }
        __syncthreads();   // staged tile visible

        // coalesced copy: 64 rows x 512 B, 16 B chunks (2048 chunks, 8/thread)
        __half* cg = ctx + (size_t)(b * S_LEN + qb * 64) * D_MODEL + h * HDIM;
        int idx = tid;
#pragma unroll
        for (int i = 0; i < 8; i++, idx += 256) {
            int row = idx >> 5;
            int c8  = (idx & 31) << 3;
            *(float4*)(cg + (size_t)row * D_MODEL + c8) =
                *(const float4*)(Qs + row * APH + c8);
        }
    }
}

// ---------------------------------------------------------------------------
// Host launch (R11 graph shape)
// ---------------------------------------------------------------------------
extern "C" void kernel_launch(void* const* d_in, const int* in_sizes, int n_in,
                              void* d_out, int out_size) {
    const float* X  = (const float*)d_in[0];
    const float* Wq = (const float*)d_in[3];
    const float* Wk = (const float*)d_in[4];
    const float* Wv = (const float*)d_in[5];
    const float* Wo = (const float*)d_in[6];
    float* out = (float*)d_out;

    __half *pX, *pWT, *pWoT, *pQKV, *pC;
    cudaGetSymbolAddress((void**)&pX,   g_X);
    cudaGetSymbolAddress((void**)&pWT,  g_WT);
    cudaGetSymbolAddress((void**)&pWoT, g_WoT);
    cudaGetSymbolAddress((void**)&pQKV, g_QKV);
    cudaGetSymbolAddress((void**)&pC,   g_ctx);

    cudaFuncSetAttribute(gemm_fp16<__half>, cudaFuncAttributeMaxDynamicSharedMemorySize, GSMEM_BYTES);
    cudaFuncSetAttribute(gemm_fp16<float>,  cudaFuncAttributeMaxDynamicSharedMemorySize, GSMEM_BYTES);
    cudaFuncSetAttribute(attn_fp16, cudaFuncAttributeMaxDynamicSharedMemorySize, ATTN_SMEM);

    static cudaStream_t s1 = nullptr, s2 = nullptr;
    static cudaEvent_t eFork = nullptr, eWqkv = nullptr, eWo = nullptr;
    if (s1 == nullptr) {
        cudaStreamCreateWithFlags(&s1, cudaStreamNonBlocking);
        cudaStreamCreateWithFlags(&s2, cudaStreamNonBlocking);
        cudaEventCreateWithFlags(&eFork, cudaEventDisableTiming);
        cudaEventCreateWithFlags(&eWqkv, cudaEventDisableTiming);
        cudaEventCreateWithFlags(&eWo,   cudaEventDisableTiming);
    }

    // fork
    cudaEventRecord(eFork, 0);
    cudaStreamWaitEvent(s1, eFork, 0);
    cudaStreamWaitEvent(s2, eFork, 0);

    // s1: fused-W transpose (QKV GEMM dep)
    transpose_qkv<<<dim3(NQKV / 32, D_MODEL / 32), dim3(32, 8), 0, s1>>>(Wq, Wk, Wv, pWT);
    cudaEventRecord(eWqkv, s1);

    // s2: Wo transpose (O-proj dep only)
    transpose_wo<<<dim3(D_MODEL / 32, D_MODEL / 32), dim3(32, 8), 0, s2>>>(Wo, pWoT, D_MODEL, D_MODEL);
    cudaEventRecord(eWo, s2);

    // s0: X -> fp16
    cvt_fp16_kernel<<<(BSTOT * D_MODEL / 4) / 256, 256>>>((const float4*)X, (__half2*)pX);

    // fused QKV projection (fp16 out)
    cudaStreamWaitEvent(0, eWqkv, 0);
    gemm_fp16<__half><<<dim3(NQKV / 128, BSTOT / 128), 256, GSMEM_BYTES>>>(pX, pWT, pQKV, NQKV, D_MODEL);

    rope_kernel<<<BSTOT, 128>>>(pQKV);

    attn_fp16<<<dim3(S_LEN / 64, B_SZ * NHEAD), 256, ATTN_SMEM>>>(pQKV, pC);

    // output projection (fp32 out)
    cudaStreamWaitEvent(0, eWo, 0);
    gemm_fp16<float><<<dim3(D_MODEL / 128, BSTOT / 128), 256, GSMEM_BYTES>>>(pC, pWoT, out, D_MODEL, D_MODEL);
}